// round 12
// baseline (speedup 1.0000x reference)
#include <cuda_runtime.h>
#include <cstdint>

// TopK per row (B=4096 x D=65536 fp32, k=64), ReLU, scatter into zeros.
// PERSISTENT kernel: 592 CTAs (4/SM), 512 threads, each CTA loops over rows.
//   - Output-row zero-fill via TMA (16 x 16KB cp.async.bulk from zeroed smem),
//     pipelined ONE ROW AHEAD: zeros for row r+1 issue before row r's rank
//     phase, so the wait at row r+1 is ~free.
//   - Hot loop per row: pure read stream (LDG.128) + FMNMX threshold detect +
//     rare candidate push to smem; exact rank of ~168 candidates; scatter k.
// Exact 3-level radix fallback for arbitrary inputs (tie-break lowest index,
// matching jax.lax.top_k); drains TMA before aliasing zbuf as histogram.

namespace {

constexpr int TPB    = 512;
constexpr int D_DIM  = 65536;
constexpr int NV     = D_DIM / 4;       // 16384 float4 per row
constexpr int U      = 4;               // float4 per thread per iter
constexpr int ITERS  = NV / (TPB * U);  // 8
constexpr int CAP    = 2048;            // candidate capacity
constexpr float THRESH = 2.8f;          // E[cnt]~168 for N(0,1), >> k=64
constexpr int ZBYTES = 16 * 1024;       // zero buffer / TMA chunk
constexpr int NCHUNK = (D_DIM * 4) / ZBYTES;   // 16 chunks per 256KB row
constexpr int NCTA   = 592;             // 4 per SM x 148 SMs
constexpr unsigned SMEM_BYTES = ZBYTES + 2u * CAP * 4u;  // 32 KB dynamic

__device__ __forceinline__ unsigned orderKey(float f) {
    unsigned u = __float_as_uint(f);
    return u ^ ((u & 0x80000000u) ? 0xFFFFFFFFu : 0x80000000u);
}

__device__ __forceinline__ void issue_zero_row(uint32_t zs, float* outf) {
    #pragma unroll
    for (int c = 0; c < NCHUNK; ++c) {
        const char* dst = reinterpret_cast<const char*>(outf) + (size_t)c * ZBYTES;
        asm volatile(
            "cp.async.bulk.global.shared::cta.bulk_group [%0], [%1], %2;"
            :: "l"(dst), "r"(zs), "r"((unsigned)ZBYTES) : "memory");
    }
    asm volatile("cp.async.bulk.commit_group;" ::: "memory");
}

__global__ void __launch_bounds__(TPB)
topk_persist_kernel(const float* __restrict__ x,
                    const int* __restrict__ kptr,
                    float* __restrict__ out,
                    int rows)
{
    extern __shared__ unsigned smem_u[];
    unsigned* zbuf = smem_u;                                   // [4096]
    float*    cval = reinterpret_cast<float*>(smem_u + ZBYTES / 4);  // [CAP]
    unsigned* cidx = smem_u + ZBYTES / 4 + CAP;                // [CAP]
    unsigned* hist = smem_u;                                   // fallback alias
    __shared__ unsigned s_cnt, s_bin, s_rank;
    __shared__ unsigned s_chunk[TPB + 1];

    const int tid    = threadIdx.x;
    const int bid    = blockIdx.x;
    const int stride = gridDim.x;
    const unsigned k = (unsigned)__ldg(kptr);

    // ---- One-time prologue: zero the TMA source buffer ----
    for (int i = tid; i < ZBYTES / 4; i += TPB) zbuf[i] = 0u;
    asm volatile("fence.proxy.async.shared::cta;" ::: "memory");
    __syncthreads();

    uint32_t zs;
    asm("{ .reg .u64 t; cvta.to.shared.u64 t, %1; cvt.u32.u64 %0, t; }"
        : "=r"(zs) : "l"(zbuf));

    // Pre-issue zeros for this CTA's first row.
    if (tid == 0 && bid < rows)
        issue_zero_row(zs, out + (size_t)bid * D_DIM);

    for (int row = bid; row < rows; row += stride) {
        const float4* rowv = reinterpret_cast<const float4*>(x) + (size_t)row * NV;
        float*        outf = out + (size_t)row * D_DIM;
        const int     next = row + stride;

        if (tid == 0) s_cnt = 0u;
        __syncthreads();

        // ---- Hot pass: pure read stream + rare candidate collect ----
        #pragma unroll
        for (int it = 0; it < ITERS; ++it) {
            const int base = tid + it * TPB * U;
            float4 v[U];
            #pragma unroll
            for (int u = 0; u < U; ++u)
                v[u] = __ldcs(&rowv[base + u * TPB]);

            float m[U];
            #pragma unroll
            for (int u = 0; u < U; ++u)
                m[u] = fmaxf(fmaxf(v[u].x, v[u].y), fmaxf(v[u].z, v[u].w));

            bool any = (m[0] >= THRESH) | (m[1] >= THRESH) |
                       (m[2] >= THRESH) | (m[3] >= THRESH);
            if (any) {                                    // rare per thread
                #pragma unroll
                for (int u = 0; u < U; ++u) {
                    if (m[u] >= THRESH) {
                        const int i = base + u * TPB;
                        float vv[4] = {v[u].x, v[u].y, v[u].z, v[u].w};
                        #pragma unroll
                        for (int l = 0; l < 4; ++l) {
                            if (vv[l] >= THRESH) {
                                unsigned p = atomicAdd(&s_cnt, 1u);
                                if (p < CAP) { cval[p] = vv[l]; cidx[p] = (unsigned)(i * 4 + l); }
                            }
                        }
                    }
                }
            }
        }
        __syncthreads();

        // ---- Pipeline: issue next row's zeros, then wait for THIS row's ----
        if (tid == 0) {
            if (next < rows) {
                issue_zero_row(zs, out + (size_t)next * D_DIM);
                asm volatile("cp.async.bulk.wait_group 1;" ::: "memory");
            } else {
                asm volatile("cp.async.bulk.wait_group 0;" ::: "memory");
            }
        }
        __syncthreads();

        const unsigned cnt = s_cnt;
        if (cnt >= k && cnt <= CAP) {
            // ---- Exact rank among candidates; direct scatter ----
            for (unsigned j = (unsigned)tid; j < cnt; j += TPB) {
                const float    vj = cval[j];
                const unsigned ij = cidx[j];
                unsigned rank = 0;
                for (unsigned t = 0; t < cnt; ++t) {
                    const float vt = cval[t];
                    rank += (vt > vj) || (vt == vj && cidx[t] < ij);
                }
                if (rank < k)
                    outf[ij] = fmaxf(vj, 0.0f);
            }
            __syncthreads();   // cval/cidx reuse safety for next row
            continue;
        }

        // ============ Exact fallback: 3-level radix refinement ============
        // Drain ALL TMA first (in-flight bulk copies still read zbuf).
        if (tid == 0)
            asm volatile("cp.async.bulk.wait_group 0;" ::: "memory");
        __syncthreads();

        const float* rowf = reinterpret_cast<const float*>(rowv);
        unsigned need = k;
        unsigned b0, b1, b2;

        // level 0: bits[31:20]
        for (int i = tid; i < 4096; i += TPB) hist[i] = 0u;
        __syncthreads();
        for (int i = tid; i < D_DIM; i += TPB)
            atomicAdd(&hist[orderKey(rowf[i]) >> 20], 1u);
        __syncthreads();
        if (tid == 0) {
            unsigned acc = 0;
            for (int b = 4095; b >= 0; --b) {
                unsigned c = hist[b];
                if (acc + c >= need) { s_bin = (unsigned)b; s_rank = need - acc; break; }
                acc += c;
            }
        }
        __syncthreads();
        b0 = s_bin; need = s_rank;

        // level 1: bits[19:8] restricted to top bits == b0
        for (int i = tid; i < 4096; i += TPB) hist[i] = 0u;
        __syncthreads();
        for (int i = tid; i < D_DIM; i += TPB) {
            unsigned key = orderKey(rowf[i]);
            if ((key >> 20) == b0) atomicAdd(&hist[(key >> 8) & 0xFFFu], 1u);
        }
        __syncthreads();
        if (tid == 0) {
            unsigned acc = 0;
            for (int b = 4095; b >= 0; --b) {
                unsigned c = hist[b];
                if (acc + c >= need) { s_bin = (unsigned)b; s_rank = need - acc; break; }
                acc += c;
            }
        }
        __syncthreads();
        b1 = s_bin; need = s_rank;

        // level 2: bits[7:0] restricted to top 24 bits
        for (int i = tid; i < 256; i += TPB) hist[i] = 0u;
        __syncthreads();
        const unsigned pre24 = (b0 << 12) | b1;
        for (int i = tid; i < D_DIM; i += TPB) {
            unsigned key = orderKey(rowf[i]);
            if ((key >> 8) == pre24) atomicAdd(&hist[key & 0xFFu], 1u);
        }
        __syncthreads();
        if (tid == 0) {
            unsigned acc = 0;
            for (int b = 255; b >= 0; --b) {
                unsigned c = hist[b];
                if (acc + c >= need) { s_bin = (unsigned)b; s_rank = need - acc; break; }
                acc += c;
            }
        }
        __syncthreads();
        b2 = s_bin; need = s_rank;                    // take `need` of key==pivot
        const unsigned pivot = (pre24 << 8) | b2;

        // winners with key > pivot: write directly
        for (int i = tid; i < D_DIM; i += TPB) {
            float v = rowf[i];
            if (orderKey(v) > pivot)
                outf[i] = fmaxf(v, 0.0f);
        }

        // key == pivot: take `need` with SMALLEST indices (jax tie rule)
        {
            const int CHUNK = D_DIM / TPB;   // 128
            unsigned local = 0;
            for (int i = tid * CHUNK; i < (tid + 1) * CHUNK; ++i)
                local += (orderKey(rowf[i]) == pivot);
            s_chunk[tid + 1] = local;
            if (tid == 0) s_chunk[0] = 0;
            __syncthreads();
            if (tid == 0)
                for (int t = 1; t <= TPB; ++t) s_chunk[t] += s_chunk[t - 1];
            __syncthreads();
            unsigned ord = s_chunk[tid];
            for (int i = tid * CHUNK; i < (tid + 1) * CHUNK; ++i) {
                float v = rowf[i];
                if (orderKey(v) == pivot) {
                    if (ord < need)
                        outf[i] = fmaxf(v, 0.0f);
                    ++ord;
                }
            }
        }
        __syncthreads();

        // Restore zbuf (hist aliased it) and re-issue next row's zeros if the
        // earlier issue raced with histogram writes was prevented by the drain;
        // zbuf must be zero again before any future TMA reads it.
        for (int i = tid; i < ZBYTES / 4; i += TPB) zbuf[i] = 0u;
        asm volatile("fence.proxy.async.shared::cta;" ::: "memory");
        __syncthreads();
        if (tid == 0 && next < rows)
            issue_zero_row(zs, out + (size_t)next * D_DIM);
        // (re-issuing is safe: writing zeros twice is idempotent)
    }
}

} // namespace

extern "C" void kernel_launch(void* const* d_in, const int* in_sizes, int n_in,
                              void* d_out, int out_size)
{
    const float* x   = (const float*)d_in[0];
    const int*   kp  = (const int*)d_in[1];
    float*       out = (float*)d_out;

    const int rows = in_sizes[0] / D_DIM;
    const int grid = (rows < NCTA) ? rows : NCTA;

    cudaFuncSetAttribute(topk_persist_kernel,
                         cudaFuncAttributeMaxDynamicSharedMemorySize, SMEM_BYTES);
    topk_persist_kernel<<<grid, TPB, SMEM_BYTES>>>(x, kp, out, rows);
}

// round 13
// speedup vs baseline: 1.0241x; 1.0241x over previous
#include <cuda_runtime.h>
#include <cstdint>

// TopK per row (B=4096 x D=65536 fp32, k=64), ReLU, scatter into zeros.
// PERSISTENT kernel: 592 CTAs (4/SM), 512 threads, each CTA loops over rows.
//   - Output-row zero-fill via TMA (16 x 16KB cp.async.bulk from zeroed smem),
//     pipelined ONE ROW AHEAD: next row's zeros issue before this row's rank
//     phase, so the wait at the next row is ~free.
//   - Hot loop per row: pure read stream (LDG.128, immediate offsets off one
//     base) + FMNMX threshold detect + rare candidate push to smem; exact
//     rank of ~168 candidates; scatter k winners.
//   - __launch_bounds__(512, 4) pins the register budget to 32 (R12 regressed
//     to 64 regs -> occ 48%).
// Exact 3-level radix fallback for arbitrary inputs (tie-break lowest index,
// matching jax.lax.top_k); drains TMA before aliasing zbuf as histogram.

namespace {

constexpr int TPB    = 512;
constexpr int D_DIM  = 65536;
constexpr int NV     = D_DIM / 4;       // 16384 float4 per row
constexpr int U      = 4;               // float4 per thread per iter
constexpr int ITERS  = NV / (TPB * U);  // 8
constexpr int CAP    = 2048;            // candidate capacity
constexpr float THRESH = 2.8f;          // E[cnt]~168 for N(0,1), >> k=64
constexpr int ZBYTES = 16 * 1024;       // zero buffer / TMA chunk
constexpr int NCHUNK = (D_DIM * 4) / ZBYTES;   // 16 chunks per 256KB row
constexpr int NCTA   = 592;             // 4 per SM x 148 SMs
constexpr unsigned SMEM_BYTES = ZBYTES + 2u * CAP * 4u;  // 32 KB dynamic

__device__ __forceinline__ unsigned orderKey(float f) {
    unsigned u = __float_as_uint(f);
    return u ^ ((u & 0x80000000u) ? 0xFFFFFFFFu : 0x80000000u);
}

__device__ __forceinline__ void issue_zero_row(uint32_t zs, float* outf) {
    #pragma unroll
    for (int c = 0; c < NCHUNK; ++c) {
        const char* dst = reinterpret_cast<const char*>(outf) + (size_t)c * ZBYTES;
        asm volatile(
            "cp.async.bulk.global.shared::cta.bulk_group [%0], [%1], %2;"
            :: "l"(dst), "r"(zs), "r"((unsigned)ZBYTES) : "memory");
    }
    asm volatile("cp.async.bulk.commit_group;" ::: "memory");
}

__global__ void __launch_bounds__(TPB, 4)
topk_persist_kernel(const float* __restrict__ x,
                    const int* __restrict__ kptr,
                    float* __restrict__ out,
                    int rows)
{
    extern __shared__ unsigned smem_u[];
    unsigned* zbuf = smem_u;                                   // [4096]
    float*    cval = reinterpret_cast<float*>(smem_u + ZBYTES / 4);  // [CAP]
    unsigned* cidx = smem_u + ZBYTES / 4 + CAP;                // [CAP]
    unsigned* hist = smem_u;                                   // fallback alias
    __shared__ unsigned s_cnt, s_bin, s_rank;
    __shared__ unsigned s_chunk[TPB + 1];

    const int tid = threadIdx.x;
    const unsigned k = (unsigned)__ldg(kptr);

    // ---- One-time prologue: zero the TMA source buffer ----
    for (int i = tid; i < ZBYTES / 4; i += TPB) zbuf[i] = 0u;
    asm volatile("fence.proxy.async.shared::cta;" ::: "memory");
    __syncthreads();

    uint32_t zs;
    asm("{ .reg .u64 t; cvta.to.shared.u64 t, %1; cvt.u32.u64 %0, t; }"
        : "=r"(zs) : "l"(zbuf));

    // Pre-issue zeros for this CTA's first row.
    if (tid == 0 && (int)blockIdx.x < rows)
        issue_zero_row(zs, out + (size_t)blockIdx.x * D_DIM);

    for (int row = blockIdx.x; row < rows; row += gridDim.x) {
        // Minimal live state: one read base, one out base, recomputed per row.
        const float4* p    = reinterpret_cast<const float4*>(x) + (size_t)row * NV + tid;
        float*        outf = out + (size_t)row * D_DIM;

        if (tid == 0) s_cnt = 0u;
        __syncthreads();

        // ---- Hot pass: pure read stream + rare candidate collect ----
        #pragma unroll
        for (int it = 0; it < ITERS; ++it) {
            float4 v[U];
            #pragma unroll
            for (int u = 0; u < U; ++u)          // imm offsets off p
                v[u] = __ldcs(p + (it * TPB * U + u * TPB));

            float m[U];
            #pragma unroll
            for (int u = 0; u < U; ++u)
                m[u] = fmaxf(fmaxf(v[u].x, v[u].y), fmaxf(v[u].z, v[u].w));

            bool any = (m[0] >= THRESH) | (m[1] >= THRESH) |
                       (m[2] >= THRESH) | (m[3] >= THRESH);
            if (any) {                                    // rare per thread
                #pragma unroll
                for (int u = 0; u < U; ++u) {
                    if (m[u] >= THRESH) {
                        const int i = tid + it * TPB * U + u * TPB;
                        float vv[4] = {v[u].x, v[u].y, v[u].z, v[u].w};
                        #pragma unroll
                        for (int l = 0; l < 4; ++l) {
                            if (vv[l] >= THRESH) {
                                unsigned pp = atomicAdd(&s_cnt, 1u);
                                if (pp < CAP) { cval[pp] = vv[l]; cidx[pp] = (unsigned)(i * 4 + l); }
                            }
                        }
                    }
                }
            }
        }
        __syncthreads();

        // ---- Pipeline: issue next row's zeros, then wait for THIS row's ----
        if (tid == 0) {
            const int next = row + gridDim.x;
            if (next < rows) {
                issue_zero_row(zs, out + (size_t)next * D_DIM);
                asm volatile("cp.async.bulk.wait_group 1;" ::: "memory");
            } else {
                asm volatile("cp.async.bulk.wait_group 0;" ::: "memory");
            }
        }
        __syncthreads();

        const unsigned cnt = s_cnt;
        if (cnt >= k && cnt <= CAP) {
            // ---- Exact rank among candidates; direct scatter ----
            for (unsigned j = (unsigned)tid; j < cnt; j += TPB) {
                const float    vj = cval[j];
                const unsigned ij = cidx[j];
                unsigned rank = 0;
                for (unsigned t = 0; t < cnt; ++t) {
                    const float vt = cval[t];
                    rank += (vt > vj) || (vt == vj && cidx[t] < ij);
                }
                if (rank < k)
                    outf[ij] = fmaxf(vj, 0.0f);
            }
            __syncthreads();   // cval/cidx reuse safety for next row
            continue;
        }

        // ============ Exact fallback: 3-level radix refinement ============
        // Drain ALL TMA first (in-flight bulk copies still read zbuf).
        if (tid == 0)
            asm volatile("cp.async.bulk.wait_group 0;" ::: "memory");
        __syncthreads();

        const float* rowf = reinterpret_cast<const float*>(p - tid);
        unsigned need = k;
        unsigned b0, b1, b2;

        // level 0: bits[31:20]
        for (int i = tid; i < 4096; i += TPB) hist[i] = 0u;
        __syncthreads();
        for (int i = tid; i < D_DIM; i += TPB)
            atomicAdd(&hist[orderKey(rowf[i]) >> 20], 1u);
        __syncthreads();
        if (tid == 0) {
            unsigned acc = 0;
            for (int b = 4095; b >= 0; --b) {
                unsigned c = hist[b];
                if (acc + c >= need) { s_bin = (unsigned)b; s_rank = need - acc; break; }
                acc += c;
            }
        }
        __syncthreads();
        b0 = s_bin; need = s_rank;

        // level 1: bits[19:8] restricted to top bits == b0
        for (int i = tid; i < 4096; i += TPB) hist[i] = 0u;
        __syncthreads();
        for (int i = tid; i < D_DIM; i += TPB) {
            unsigned key = orderKey(rowf[i]);
            if ((key >> 20) == b0) atomicAdd(&hist[(key >> 8) & 0xFFFu], 1u);
        }
        __syncthreads();
        if (tid == 0) {
            unsigned acc = 0;
            for (int b = 4095; b >= 0; --b) {
                unsigned c = hist[b];
                if (acc + c >= need) { s_bin = (unsigned)b; s_rank = need - acc; break; }
                acc += c;
            }
        }
        __syncthreads();
        b1 = s_bin; need = s_rank;

        // level 2: bits[7:0] restricted to top 24 bits
        for (int i = tid; i < 256; i += TPB) hist[i] = 0u;
        __syncthreads();
        const unsigned pre24 = (b0 << 12) | b1;
        for (int i = tid; i < D_DIM; i += TPB) {
            unsigned key = orderKey(rowf[i]);
            if ((key >> 8) == pre24) atomicAdd(&hist[key & 0xFFu], 1u);
        }
        __syncthreads();
        if (tid == 0) {
            unsigned acc = 0;
            for (int b = 255; b >= 0; --b) {
                unsigned c = hist[b];
                if (acc + c >= need) { s_bin = (unsigned)b; s_rank = need - acc; break; }
                acc += c;
            }
        }
        __syncthreads();
        b2 = s_bin; need = s_rank;                    // take `need` of key==pivot
        const unsigned pivot = (pre24 << 8) | b2;

        // winners with key > pivot: write directly
        for (int i = tid; i < D_DIM; i += TPB) {
            float v = rowf[i];
            if (orderKey(v) > pivot)
                outf[i] = fmaxf(v, 0.0f);
        }

        // key == pivot: take `need` with SMALLEST indices (jax tie rule)
        {
            const int CHUNK = D_DIM / TPB;   // 128
            unsigned local = 0;
            for (int i = tid * CHUNK; i < (tid + 1) * CHUNK; ++i)
                local += (orderKey(rowf[i]) == pivot);
            s_chunk[tid + 1] = local;
            if (tid == 0) s_chunk[0] = 0;
            __syncthreads();
            if (tid == 0)
                for (int t = 1; t <= TPB; ++t) s_chunk[t] += s_chunk[t - 1];
            __syncthreads();
            unsigned ord = s_chunk[tid];
            for (int i = tid * CHUNK; i < (tid + 1) * CHUNK; ++i) {
                float v = rowf[i];
                if (orderKey(v) == pivot) {
                    if (ord < need)
                        outf[i] = fmaxf(v, 0.0f);
                    ++ord;
                }
            }
        }
        __syncthreads();

        // Restore zbuf (hist aliased it), fence, re-issue next row's zeros
        // (idempotent; next row's winners are written on its own iteration).
        for (int i = tid; i < ZBYTES / 4; i += TPB) zbuf[i] = 0u;
        asm volatile("fence.proxy.async.shared::cta;" ::: "memory");
        __syncthreads();
        if (tid == 0) {
            const int next = row + gridDim.x;
            if (next < rows)
                issue_zero_row(zs, out + (size_t)next * D_DIM);
        }
    }
}

} // namespace

extern "C" void kernel_launch(void* const* d_in, const int* in_sizes, int n_in,
                              void* d_out, int out_size)
{
    const float* x   = (const float*)d_in[0];
    const int*   kp  = (const int*)d_in[1];
    float*       out = (float*)d_out;

    const int rows = in_sizes[0] / D_DIM;
    const int grid = (rows < NCTA) ? rows : NCTA;

    cudaFuncSetAttribute(topk_persist_kernel,
                         cudaFuncAttributeMaxDynamicSharedMemorySize, SMEM_BYTES);
    topk_persist_kernel<<<grid, TPB, SMEM_BYTES>>>(x, kp, out, rows);
}

// round 14
// speedup vs baseline: 1.0701x; 1.0450x over previous
#include <cuda_runtime.h>
#include <cstdint>

// TopK per row (B=4096 x D=65536 fp32, k=64), ReLU, scatter into zeros.
// Main kernel (one CTA per row, 512 thr, 4/SM):
//   - TMA zero-fill of the output row (16 x 16KB cp.async.bulk from zeroed
//     smem) issued at row start, draining in background. NEVER waited on
//     before work: winners go to a compact global buffer, not to the row.
//   - Hot loop: pure read stream (LDG.128) + FMNMX threshold detect + rare
//     candidate push to smem; exact rank of ~168 candidates; compact emit.
//   - cp.async.bulk.wait_group 0 is the LAST thing the CTA does (exit guard).
// Scatter kernel: ordered after main by kernel boundary (which also makes the
// TMA zero-writes visible); writes k winners per row.
// Exact 3-level radix fallback (tie-break lowest index, jax.lax.top_k rule)
// also emits compactly; never triggers on N(0,1) data.

namespace {

constexpr int TPB    = 512;
constexpr int D_DIM  = 65536;
constexpr int NV     = D_DIM / 4;       // 16384 float4 per row
constexpr int U      = 4;               // float4 per thread per iter
constexpr int ITERS  = NV / (TPB * U);  // 8
constexpr int CAP    = 2048;            // candidate capacity
constexpr float THRESH = 2.8f;          // E[cnt]~168 for N(0,1), >> k=64
constexpr int ZBYTES = 16 * 1024;       // zero buffer / TMA chunk
constexpr int NCHUNK = (D_DIM * 4) / ZBYTES;   // 16 chunks per 256KB row
constexpr int SLOT   = 256;             // winner slots per row
constexpr int MAXROWS = 4096;
constexpr unsigned SMEM_BYTES = ZBYTES + 2u * CAP * 4u;  // 32 KB dynamic

__device__ float    g_val[MAXROWS * SLOT];
__device__ unsigned g_idx[MAXROWS * SLOT];

__device__ __forceinline__ unsigned orderKey(float f) {
    unsigned u = __float_as_uint(f);
    return u ^ ((u & 0x80000000u) ? 0xFFFFFFFFu : 0x80000000u);
}

__global__ void __launch_bounds__(TPB)
topk_main_kernel(const float* __restrict__ x,
                 const int* __restrict__ kptr,
                 float* __restrict__ out)
{
    extern __shared__ unsigned smem_u[];
    unsigned* zbuf = smem_u;                                   // [4096]
    float*    cval = reinterpret_cast<float*>(smem_u + ZBYTES / 4);  // [CAP]
    unsigned* cidx = smem_u + ZBYTES / 4 + CAP;                // [CAP]
    unsigned* hist = smem_u;   // fallback alias (TMA drained before use)
    __shared__ unsigned s_cnt, s_bin, s_rank;
    __shared__ unsigned s_chunk[TPB + 1];

    const int tid = threadIdx.x;
    const int row = blockIdx.x;
    const unsigned k = (unsigned)__ldg(kptr);
    const unsigned kw = min(k, (unsigned)SLOT);

    const float4* rowv = reinterpret_cast<const float4*>(x) + (size_t)row * NV;
    float*    outf = out + (size_t)row * D_DIM;
    float*    gval = g_val + (size_t)row * SLOT;
    unsigned* gidx = g_idx + (size_t)row * SLOT;

    // ---- Zero smem buffer, then launch background TMA zero stores ----
    for (int i = tid; i < ZBYTES / 4; i += TPB) zbuf[i] = 0u;
    if (tid == 0) s_cnt = 0u;
    asm volatile("fence.proxy.async.shared::cta;" ::: "memory");
    __syncthreads();

    uint32_t zs;
    asm("{ .reg .u64 t; cvta.to.shared.u64 t, %1; cvt.u32.u64 %0, t; }"
        : "=r"(zs) : "l"(zbuf));
    if (tid == 0) {
        #pragma unroll
        for (int c = 0; c < NCHUNK; ++c) {
            const char* dst = reinterpret_cast<const char*>(outf) + (size_t)c * ZBYTES;
            asm volatile(
                "cp.async.bulk.global.shared::cta.bulk_group [%0], [%1], %2;"
                :: "l"(dst), "r"(zs), "r"((unsigned)ZBYTES) : "memory");
        }
        asm volatile("cp.async.bulk.commit_group;" ::: "memory");
    }

    // ---- Hot pass: pure read stream + rare candidate collect ----
    #pragma unroll
    for (int it = 0; it < ITERS; ++it) {
        const int base = tid + it * TPB * U;
        float4 v[U];
        #pragma unroll
        for (int u = 0; u < U; ++u)
            v[u] = __ldcs(&rowv[base + u * TPB]);

        float m[U];
        #pragma unroll
        for (int u = 0; u < U; ++u)
            m[u] = fmaxf(fmaxf(v[u].x, v[u].y), fmaxf(v[u].z, v[u].w));

        bool any = (m[0] >= THRESH) | (m[1] >= THRESH) |
                   (m[2] >= THRESH) | (m[3] >= THRESH);
        if (any) {                                    // rare per thread
            #pragma unroll
            for (int u = 0; u < U; ++u) {
                if (m[u] >= THRESH) {
                    const int i = base + u * TPB;
                    float vv[4] = {v[u].x, v[u].y, v[u].z, v[u].w};
                    #pragma unroll
                    for (int l = 0; l < 4; ++l) {
                        if (vv[l] >= THRESH) {
                            unsigned p = atomicAdd(&s_cnt, 1u);
                            if (p < CAP) { cval[p] = vv[l]; cidx[p] = (unsigned)(i * 4 + l); }
                        }
                    }
                }
            }
        }
    }
    __syncthreads();

    const unsigned cnt = s_cnt;
    if (cnt >= k && cnt <= CAP) {
        // ---- Exact rank among candidates; compact emit (rank = slot) ----
        for (unsigned j = (unsigned)tid; j < cnt; j += TPB) {
            const float    vj = cval[j];
            const unsigned ij = cidx[j];
            unsigned rank = 0;
            for (unsigned t = 0; t < cnt; ++t) {
                const float vt = cval[t];
                rank += (vt > vj) || (vt == vj && cidx[t] < ij);
            }
            if (rank < kw) { gval[rank] = fmaxf(vj, 0.0f); gidx[rank] = ij; }
        }
        // Exit guard only: drain TMA before CTA retires (no work gated on it).
        if (tid == 0)
            asm volatile("cp.async.bulk.wait_group 0;" ::: "memory");
        return;
    }

    // ============ Exact fallback: 3-level radix refinement ============
    // Drain TMA first: hist aliases zbuf which in-flight bulk copies read.
    if (tid == 0)
        asm volatile("cp.async.bulk.wait_group 0;" ::: "memory");
    __syncthreads();

    const float* rowf = reinterpret_cast<const float*>(rowv);
    unsigned need = k;
    unsigned b0, b1, b2;

    // level 0: bits[31:20]
    for (int i = tid; i < 4096; i += TPB) hist[i] = 0u;
    __syncthreads();
    for (int i = tid; i < D_DIM; i += TPB)
        atomicAdd(&hist[orderKey(rowf[i]) >> 20], 1u);
    __syncthreads();
    if (tid == 0) {
        unsigned acc = 0;
        for (int b = 4095; b >= 0; --b) {
            unsigned c = hist[b];
            if (acc + c >= need) { s_bin = (unsigned)b; s_rank = need - acc; break; }
            acc += c;
        }
    }
    __syncthreads();
    b0 = s_bin; need = s_rank;

    // level 1: bits[19:8] restricted to top bits == b0
    for (int i = tid; i < 4096; i += TPB) hist[i] = 0u;
    __syncthreads();
    for (int i = tid; i < D_DIM; i += TPB) {
        unsigned key = orderKey(rowf[i]);
        if ((key >> 20) == b0) atomicAdd(&hist[(key >> 8) & 0xFFFu], 1u);
    }
    __syncthreads();
    if (tid == 0) {
        unsigned acc = 0;
        for (int b = 4095; b >= 0; --b) {
            unsigned c = hist[b];
            if (acc + c >= need) { s_bin = (unsigned)b; s_rank = need - acc; break; }
            acc += c;
        }
    }
    __syncthreads();
    b1 = s_bin; need = s_rank;

    // level 2: bits[7:0] restricted to top 24 bits
    for (int i = tid; i < 256; i += TPB) hist[i] = 0u;
    __syncthreads();
    const unsigned pre24 = (b0 << 12) | b1;
    for (int i = tid; i < D_DIM; i += TPB) {
        unsigned key = orderKey(rowf[i]);
        if ((key >> 8) == pre24) atomicAdd(&hist[key & 0xFFu], 1u);
    }
    __syncthreads();
    if (tid == 0) {
        unsigned acc = 0;
        for (int b = 255; b >= 0; --b) {
            unsigned c = hist[b];
            if (acc + c >= need) { s_bin = (unsigned)b; s_rank = need - acc; break; }
            acc += c;
        }
        s_cnt = 0u;
    }
    __syncthreads();
    b2 = s_bin; need = s_rank;                    // take `need` of key==pivot
    const unsigned pivot = (pre24 << 8) | b2;

    // winners with key > pivot: compact emit
    for (int i = tid; i < D_DIM; i += TPB) {
        float v = rowf[i];
        if (orderKey(v) > pivot) {
            unsigned p = atomicAdd(&s_cnt, 1u);
            if (p < kw) { gval[p] = fmaxf(v, 0.0f); gidx[p] = (unsigned)i; }
        }
    }
    __syncthreads();

    // key == pivot: take `need` with SMALLEST indices (jax tie rule)
    {
        const int CHUNK = D_DIM / TPB;   // 128
        unsigned local = 0;
        for (int i = tid * CHUNK; i < (tid + 1) * CHUNK; ++i)
            local += (orderKey(rowf[i]) == pivot);
        s_chunk[tid + 1] = local;
        if (tid == 0) s_chunk[0] = 0;
        __syncthreads();
        if (tid == 0)
            for (int t = 1; t <= TPB; ++t) s_chunk[t] += s_chunk[t - 1];
        __syncthreads();
        unsigned ord = s_chunk[tid];
        for (int i = tid * CHUNK; i < (tid + 1) * CHUNK; ++i) {
            float v = rowf[i];
            if (orderKey(v) == pivot) {
                if (ord < need) {
                    unsigned p = atomicAdd(&s_cnt, 1u);
                    if (p < kw) { gval[p] = fmaxf(v, 0.0f); gidx[p] = (unsigned)i; }
                }
                ++ord;
            }
        }
    }
}

// ---------------------------------------------------------------- scatter
__global__ void __launch_bounds__(SLOT)
scatter_kernel(const int* __restrict__ kptr, float* __restrict__ out)
{
    const int row = blockIdx.x;
    const unsigned j = threadIdx.x;
    const unsigned k = (unsigned)__ldg(kptr);
    if (j < min(k, (unsigned)SLOT)) {
        unsigned idx = g_idx[(size_t)row * SLOT + j];
        out[(size_t)row * D_DIM + idx] = g_val[(size_t)row * SLOT + j];
    }
}

} // namespace

extern "C" void kernel_launch(void* const* d_in, const int* in_sizes, int n_in,
                              void* d_out, int out_size)
{
    const float* x   = (const float*)d_in[0];
    const int*   kp  = (const int*)d_in[1];
    float*       out = (float*)d_out;

    const int rows = in_sizes[0] / D_DIM;

    cudaFuncSetAttribute(topk_main_kernel,
                         cudaFuncAttributeMaxDynamicSharedMemorySize, SMEM_BYTES);
    topk_main_kernel<<<rows, TPB, SMEM_BYTES>>>(x, kp, out);
    scatter_kernel<<<rows, SLOT>>>(kp, out);
}

// round 15
// speedup vs baseline: 1.1230x; 1.0494x over previous
#include <cuda_runtime.h>
#include <cstdint>

// TopK per row (B=4096 x D=65536 fp32, k=64), ReLU, scatter into zeros.
// R10 configuration with ONE change: hot-loop loads are plain cached LDG.128
// (was __ldcs). Theory: the read path capped at ~3.1 TB/s under .cs policy
// while plain-load streams reached ~4.6 TB/s (R1) and the write path does 7.
//   - One CTA per row, 512 threads, 4 CTAs/SM.
//   - TMA zero-fill of output row (16 x 16KB cp.async.bulk from zeroed smem)
//     issued at row start, drains in background during the read loop.
//   - Hot loop: pure read stream + FMNMX threshold detect + rare candidate
//     push to smem; exact rank of ~168 candidates; direct scatter after
//     cp.async.bulk.wait_group 0.
// Exact 3-level radix fallback (tie-break lowest index, jax.lax.top_k rule);
// never triggers on N(0,1) data.

namespace {

constexpr int TPB    = 512;
constexpr int D_DIM  = 65536;
constexpr int NV     = D_DIM / 4;       // 16384 float4 per row
constexpr int U      = 4;               // float4 per thread per iter
constexpr int ITERS  = NV / (TPB * U);  // 8
constexpr int CAP    = 2048;            // candidate capacity
constexpr float THRESH = 2.8f;          // E[cnt]~168 for N(0,1), >> k=64
constexpr int ZBYTES = 16 * 1024;       // zero buffer / TMA chunk
constexpr int NCHUNK = (D_DIM * 4) / ZBYTES;   // 16 chunks per 256KB row
constexpr unsigned SMEM_BYTES = ZBYTES + 2u * CAP * 4u;  // 32 KB dynamic

__device__ __forceinline__ unsigned orderKey(float f) {
    unsigned u = __float_as_uint(f);
    return u ^ ((u & 0x80000000u) ? 0xFFFFFFFFu : 0x80000000u);
}

__global__ void __launch_bounds__(TPB)
topk_tma_kernel(const float* __restrict__ x,
                const int* __restrict__ kptr,
                float* __restrict__ out)
{
    extern __shared__ unsigned smem_u[];
    unsigned* zbuf = smem_u;                                   // [4096]
    float*    cval = reinterpret_cast<float*>(smem_u + ZBYTES / 4);  // [CAP]
    unsigned* cidx = smem_u + ZBYTES / 4 + CAP;                // [CAP]
    unsigned* hist = smem_u;   // fallback alias (TMA drained before use)
    __shared__ unsigned s_cnt, s_bin, s_rank;
    __shared__ unsigned s_chunk[TPB + 1];

    const int tid = threadIdx.x;
    const int row = blockIdx.x;
    const unsigned k = (unsigned)__ldg(kptr);

    const float4* rowv = reinterpret_cast<const float4*>(x) + (size_t)row * NV;
    float*        outf = out + (size_t)row * D_DIM;

    // ---- Zero smem buffer, then launch background TMA zero stores ----
    for (int i = tid; i < ZBYTES / 4; i += TPB) zbuf[i] = 0u;
    if (tid == 0) s_cnt = 0u;
    asm volatile("fence.proxy.async.shared::cta;" ::: "memory");
    __syncthreads();

    if (tid == 0) {
        uint32_t zs;
        asm("{ .reg .u64 t; cvta.to.shared.u64 t, %1; cvt.u32.u64 %0, t; }"
            : "=r"(zs) : "l"(zbuf));
        #pragma unroll
        for (int c = 0; c < NCHUNK; ++c) {
            const char* dst = reinterpret_cast<const char*>(outf) + (size_t)c * ZBYTES;
            asm volatile(
                "cp.async.bulk.global.shared::cta.bulk_group [%0], [%1], %2;"
                :: "l"(dst), "r"(zs), "r"((unsigned)ZBYTES) : "memory");
        }
        asm volatile("cp.async.bulk.commit_group;" ::: "memory");
    }

    // ---- Hot pass: pure read stream (PLAIN cached loads) + rare collect ----
    #pragma unroll
    for (int it = 0; it < ITERS; ++it) {
        const int base = tid + it * TPB * U;
        float4 v[U];
        #pragma unroll
        for (int u = 0; u < U; ++u)
            v[u] = rowv[base + u * TPB];          // plain LDG.E.128

        float m[U];
        #pragma unroll
        for (int u = 0; u < U; ++u)
            m[u] = fmaxf(fmaxf(v[u].x, v[u].y), fmaxf(v[u].z, v[u].w));

        bool any = (m[0] >= THRESH) | (m[1] >= THRESH) |
                   (m[2] >= THRESH) | (m[3] >= THRESH);
        if (any) {                                    // rare per thread
            #pragma unroll
            for (int u = 0; u < U; ++u) {
                if (m[u] >= THRESH) {
                    const int i = base + u * TPB;
                    float vv[4] = {v[u].x, v[u].y, v[u].z, v[u].w};
                    #pragma unroll
                    for (int l = 0; l < 4; ++l) {
                        if (vv[l] >= THRESH) {
                            unsigned p = atomicAdd(&s_cnt, 1u);
                            if (p < CAP) { cval[p] = vv[l]; cidx[p] = (unsigned)(i * 4 + l); }
                        }
                    }
                }
            }
        }
    }
    __syncthreads();

    // ---- Zero stores must land before any winner scatter ----
    if (tid == 0)
        asm volatile("cp.async.bulk.wait_group 0;" ::: "memory");
    __syncthreads();

    const unsigned cnt = s_cnt;
    if (cnt >= k && cnt <= CAP) {
        // exact rank among candidates; direct scatter
        for (unsigned j = (unsigned)tid; j < cnt; j += TPB) {
            const float    vj = cval[j];
            const unsigned ij = cidx[j];
            unsigned rank = 0;
            for (unsigned t = 0; t < cnt; ++t) {
                const float vt = cval[t];
                rank += (vt > vj) || (vt == vj && cidx[t] < ij);
            }
            if (rank < k)
                outf[ij] = fmaxf(vj, 0.0f);
        }
        return;
    }

    // ============== Exact fallback: 3-level radix refinement ==============
    const float* rowf = reinterpret_cast<const float*>(rowv);
    unsigned need = k;
    unsigned b0, b1, b2;

    // level 0: bits[31:20]
    for (int i = tid; i < 4096; i += TPB) hist[i] = 0u;
    __syncthreads();
    for (int i = tid; i < D_DIM; i += TPB)
        atomicAdd(&hist[orderKey(rowf[i]) >> 20], 1u);
    __syncthreads();
    if (tid == 0) {
        unsigned acc = 0;
        for (int b = 4095; b >= 0; --b) {
            unsigned c = hist[b];
            if (acc + c >= need) { s_bin = (unsigned)b; s_rank = need - acc; break; }
            acc += c;
        }
    }
    __syncthreads();
    b0 = s_bin; need = s_rank;

    // level 1: bits[19:8] restricted to top bits == b0
    for (int i = tid; i < 4096; i += TPB) hist[i] = 0u;
    __syncthreads();
    for (int i = tid; i < D_DIM; i += TPB) {
        unsigned key = orderKey(rowf[i]);
        if ((key >> 20) == b0) atomicAdd(&hist[(key >> 8) & 0xFFFu], 1u);
    }
    __syncthreads();
    if (tid == 0) {
        unsigned acc = 0;
        for (int b = 4095; b >= 0; --b) {
            unsigned c = hist[b];
            if (acc + c >= need) { s_bin = (unsigned)b; s_rank = need - acc; break; }
            acc += c;
        }
    }
    __syncthreads();
    b1 = s_bin; need = s_rank;

    // level 2: bits[7:0] restricted to top 24 bits
    for (int i = tid; i < 256; i += TPB) hist[i] = 0u;
    __syncthreads();
    const unsigned pre24 = (b0 << 12) | b1;
    for (int i = tid; i < D_DIM; i += TPB) {
        unsigned key = orderKey(rowf[i]);
        if ((key >> 8) == pre24) atomicAdd(&hist[key & 0xFFu], 1u);
    }
    __syncthreads();
    if (tid == 0) {
        unsigned acc = 0;
        for (int b = 255; b >= 0; --b) {
            unsigned c = hist[b];
            if (acc + c >= need) { s_bin = (unsigned)b; s_rank = need - acc; break; }
            acc += c;
        }
    }
    __syncthreads();
    b2 = s_bin; need = s_rank;                    // take `need` of key==pivot
    const unsigned pivot = (pre24 << 8) | b2;

    // winners with key > pivot: write directly
    for (int i = tid; i < D_DIM; i += TPB) {
        float v = rowf[i];
        if (orderKey(v) > pivot)
            outf[i] = fmaxf(v, 0.0f);
    }

    // key == pivot: take `need` with SMALLEST indices (jax tie rule)
    {
        const int CHUNK = D_DIM / TPB;   // 128
        unsigned local = 0;
        for (int i = tid * CHUNK; i < (tid + 1) * CHUNK; ++i)
            local += (orderKey(rowf[i]) == pivot);
        s_chunk[tid + 1] = local;
        if (tid == 0) s_chunk[0] = 0;
        __syncthreads();
        if (tid == 0)
            for (int t = 1; t <= TPB; ++t) s_chunk[t] += s_chunk[t - 1];
        __syncthreads();
        unsigned ord = s_chunk[tid];
        for (int i = tid * CHUNK; i < (tid + 1) * CHUNK; ++i) {
            float v = rowf[i];
            if (orderKey(v) == pivot) {
                if (ord < need)
                    outf[i] = fmaxf(v, 0.0f);
                ++ord;
            }
        }
    }
}

} // namespace

extern "C" void kernel_launch(void* const* d_in, const int* in_sizes, int n_in,
                              void* d_out, int out_size)
{
    const float* x   = (const float*)d_in[0];
    const int*   kp  = (const int*)d_in[1];
    float*       out = (float*)d_out;

    const int rows = in_sizes[0] / D_DIM;

    cudaFuncSetAttribute(topk_tma_kernel,
                         cudaFuncAttributeMaxDynamicSharedMemorySize, SMEM_BYTES);
    topk_tma_kernel<<<rows, TPB, SMEM_BYTES>>>(x, kp, out);
}